// round 1
// baseline (speedup 1.0000x reference)
#include <cuda_runtime.h>
#include <math.h>

#define BATCHN 2048
#define SEQN   512
#define INPN   128
#define HIDN   256
#define OUTN   64
#define ROWS   16      // batch rows per CTA
#define NTHR   512     // 16 warps: warp w owns row w in phase B
#define HPAD   18      // padded row stride for [k][r] smem arrays (even for LDS.64 align)
#define FEPS   1e-8f

__device__ __forceinline__ float wsum(float v) {
    v += __shfl_xor_sync(0xffffffffu, v, 16);
    v += __shfl_xor_sync(0xffffffffu, v, 8);
    v += __shfl_xor_sync(0xffffffffu, v, 4);
    v += __shfl_xor_sync(0xffffffffu, v, 2);
    v += __shfl_xor_sync(0xffffffffu, v, 1);
    return v;
}

__global__ void __launch_bounds__(NTHR, 1) nlnn_kernel(
    const float* __restrict__ x,        // [B, S, 128]
    const float* __restrict__ h_init,   // [B, 256]
    const float* __restrict__ Win,      // [128, 256]
    const float* __restrict__ Wrec,     // [256, 256]
    const float* __restrict__ Wout,     // [256, 64]
    const float* __restrict__ lam_i,    // [256]
    const float* __restrict__ lam_r,    // [256]
    const float* __restrict__ s_z_p,    // [1]
    const float* __restrict__ alpha_raw,// [256]
    float* __restrict__ outp,           // [B, S, 64]
    float* __restrict__ hfin)           // [B, 256] or null
{
    __shared__ float hs[HIDN * HPAD];   // h[k][r]
    __shared__ float xs[INPN * HPAD];   // x[k][r]
    __shared__ float vs[ROWS * HIDN];   // v[r][j]

    const int tid  = threadIdx.x;
    const int b0   = blockIdx.x * ROWS;

    // GEMM-phase mapping: 64 j-groups (4 cols) x 8 row-groups (2 rows)
    const int jg = tid & 63;
    const int rg = tid >> 6;
    const int j4 = jg * 4;
    const int r2 = rg * 2;

    // Row-warp mapping: warp w <-> batch row w of this CTA
    const int w    = tid >> 5;
    const int lane = tid & 31;

    // Persistent per-row state: lane holds h[row][lane + 32*i]
    float hh[8];
    float al[8];
#pragma unroll
    for (int i = 0; i < 8; ++i) {
        int j = lane + 32 * i;
        hh[i] = h_init[(size_t)(b0 + w) * HIDN + j];
        float a = alpha_raw[j];
        al[i] = 1.0f / (1.0f + expf(-a));
    }
#pragma unroll
    for (int i = 0; i < 8; ++i)
        hs[(lane + 32 * i) * HPAD + w] = hh[i];

    const float4 liv = *(const float4*)(lam_i + j4);
    const float4 lrv = *(const float4*)(lam_r + j4);
    const float  s_z = s_z_p[0];

    const float* __restrict__ wi = Win  + j4;
    const float* __restrict__ wr = Wrec + j4;
    const float* __restrict__ wo = Wout + 2 * lane;

    __syncthreads();

    for (int t = 0; t < SEQN; ++t) {
        // ---- load x_t (warp w loads row w, coalesced) ----
        {
            int k4 = lane * 4;
            float4 xv = *(const float4*)(x + ((size_t)(b0 + w) * SEQN + t) * INPN + k4);
            xs[(k4 + 0) * HPAD + w] = xv.x;
            xs[(k4 + 1) * HPAD + w] = xv.y;
            xs[(k4 + 2) * HPAD + w] = xv.z;
            xs[(k4 + 3) * HPAD + w] = xv.w;
        }
        __syncthreads();

        // ---- input GEMM: acc = x_t @ Win (2 rows x 4 cols per thread) ----
        float a00 = 0.f, a01 = 0.f, a02 = 0.f, a03 = 0.f;
        float a10 = 0.f, a11 = 0.f, a12 = 0.f, a13 = 0.f;
#pragma unroll 8
        for (int k = 0; k < INPN; ++k) {
            float4 wv = *(const float4*)(wi + (size_t)k * HIDN);
            float2 hv = *(const float2*)(&xs[k * HPAD + r2]);
            a00 = fmaf(hv.x, wv.x, a00); a01 = fmaf(hv.x, wv.y, a01);
            a02 = fmaf(hv.x, wv.z, a02); a03 = fmaf(hv.x, wv.w, a03);
            a10 = fmaf(hv.y, wv.x, a10); a11 = fmaf(hv.y, wv.y, a11);
            a12 = fmaf(hv.y, wv.z, a12); a13 = fmaf(hv.y, wv.w, a13);
        }
        float v00 = liv.x * a00, v01 = liv.y * a01, v02 = liv.z * a02, v03 = liv.w * a03;
        float v10 = liv.x * a10, v11 = liv.y * a11, v12 = liv.z * a12, v13 = liv.w * a13;

        // ---- recurrent GEMM: acc = h_t @ Wrec ----
        a00 = a01 = a02 = a03 = a10 = a11 = a12 = a13 = 0.f;
#pragma unroll 8
        for (int k = 0; k < HIDN; ++k) {
            float4 wv = *(const float4*)(wr + (size_t)k * HIDN);
            float2 hv = *(const float2*)(&hs[k * HPAD + r2]);
            a00 = fmaf(hv.x, wv.x, a00); a01 = fmaf(hv.x, wv.y, a01);
            a02 = fmaf(hv.x, wv.z, a02); a03 = fmaf(hv.x, wv.w, a03);
            a10 = fmaf(hv.y, wv.x, a10); a11 = fmaf(hv.y, wv.y, a11);
            a12 = fmaf(hv.y, wv.z, a12); a13 = fmaf(hv.y, wv.w, a13);
        }
        v00 = fmaf(lrv.x, a00, v00); v01 = fmaf(lrv.y, a01, v01);
        v02 = fmaf(lrv.z, a02, v02); v03 = fmaf(lrv.w, a03, v03);
        v10 = fmaf(lrv.x, a10, v10); v11 = fmaf(lrv.y, a11, v11);
        v12 = fmaf(lrv.z, a12, v12); v13 = fmaf(lrv.w, a13, v13);

        *(float4*)(&vs[(r2 + 0) * HIDN + j4]) = make_float4(v00, v01, v02, v03);
        *(float4*)(&vs[(r2 + 1) * HIDN + j4]) = make_float4(v10, v11, v12, v13);
        __syncthreads();

        // ---- phase B: warp w processes row w ----
        float vv[8];
        float ssq = 0.f;
#pragma unroll
        for (int i = 0; i < 8; ++i) {
            vv[i] = vs[w * HIDN + lane + 32 * i];
            ssq = fmaf(vv[i], vv[i], ssq);
        }
        ssq = wsum(ssq);
        float ninv = 1.0f / (sqrtf(ssq) + FEPS);

        float hsq = 0.f;
#pragma unroll
        for (int i = 0; i < 8; ++i) hsq = fmaf(hh[i], hh[i], hsq);
        hsq = wsum(hsq);
        float hinv = 1.0f / (sqrtf(hsq) + FEPS);

        float dot = 0.f;
        float hn[8], ht[8];
#pragma unroll
        for (int i = 0; i < 8; ++i) {
            hn[i] = vv[i] * ninv;
            ht[i] = hh[i] * hinv;
            dot = fmaf(ht[i], hn[i], dot);
        }
        dot = wsum(dot);
        dot = fminf(fmaxf(dot, -1.0f + FEPS), 1.0f - FEPS);
        float theta = acosf(dot);
        float st    = __sinf(theta);
        float inv_st = 1.0f / (st + FEPS);
        bool  mask   = (st > FEPS);

        float res[8];
        float rsq = 0.f;
#pragma unroll
        for (int i = 0; i < 8; ++i) {
            float ct = __sinf((1.0f - al[i]) * theta) * inv_st;
            float cn = __sinf(al[i] * theta) * inv_st;
            float r  = fmaf(ct, ht[i], cn * hn[i]);
            r = mask ? r : hn[i];
            res[i] = r;
            rsq = fmaf(r, r, rsq);
        }
        rsq = wsum(rsq);
        float rinv = 1.0f / (sqrtf(rsq) + FEPS);
#pragma unroll
        for (int i = 0; i < 8; ++i) {
            hh[i] = res[i] * rinv;
            hs[(lane + 32 * i) * HPAD + w] = hh[i];   // for next step's GEMM
        }

        // ---- output GEMM: out[w][2*lane .. 2*lane+1], h broadcast via shuffle ----
        float o0 = 0.f, o1 = 0.f;
#pragma unroll
        for (int i = 0; i < 8; ++i) {
#pragma unroll
            for (int src = 0; src < 32; ++src) {
                float hk = __shfl_sync(0xffffffffu, hh[i], src);
                int k = src + 32 * i;
                float2 w2 = *(const float2*)(wo + (size_t)k * OUTN);
                o0 = fmaf(hk, w2.x, o0);
                o1 = fmaf(hk, w2.y, o1);
            }
        }
        *(float2*)(outp + ((size_t)(b0 + w) * SEQN + t) * OUTN + 2 * lane)
            = make_float2(s_z * o0, s_z * o1);
        // hs writes above are consumed only after next loop's __syncthreads()
    }

    if (hfin) {
#pragma unroll
        for (int i = 0; i < 8; ++i)
            hfin[(size_t)(b0 + w) * HIDN + lane + 32 * i] = hh[i];
    }
}

extern "C" void kernel_launch(void* const* d_in, const int* in_sizes, int n_in,
                              void* d_out, int out_size) {
    const float* x      = (const float*)d_in[0];
    const float* h_init = (const float*)d_in[1];
    const float* Win    = (const float*)d_in[2];
    const float* Wrec   = (const float*)d_in[3];
    const float* Wout   = (const float*)d_in[4];
    const float* li     = (const float*)d_in[5];
    const float* lr     = (const float*)d_in[6];
    const float* sz     = (const float*)d_in[7];
    const float* ar     = (const float*)d_in[8];

    float* outp = (float*)d_out;
    long long main_elems = (long long)BATCHN * SEQN * OUTN;
    float* hfin = nullptr;
    if ((long long)out_size >= main_elems + (long long)BATCHN * HIDN)
        hfin = outp + main_elems;

    nlnn_kernel<<<BATCHN / ROWS, NTHR>>>(x, h_init, Win, Wrec, Wout,
                                         li, lr, sz, ar, outp, hfin);
}